// round 14
// baseline (speedup 1.0000x reference)
#include <cuda_runtime.h>
#include <cuda_fp16.h>

// image [8,16,512,512] f32, flow [8,2,512,512] f32, out [8,16,512,512] f32
#define BB 8
#define CC 16
#define HH 512
#define WW 512
#define HWSZ (HH * WW)

// fp16 NHWC scratch with 32B front/back pads (zero-initialized, never written).
// Record = 16 ch * 2B = 32B per pixel.
__device__ __align__(16) __half g_buf[16 + (size_t)BB * HWSZ * CC + 16];

// ---------------------------------------------------------------------------
// Kernel 1: NCHW f32 -> NHWC fp16, all batches. Thread-per-pixel.
// (round-10 body; launch bounds force >=6 CTAs/SM for latency cover)
// ---------------------------------------------------------------------------
__global__ __launch_bounds__(256, 6) void transpose_kernel(
    const float* __restrict__ img)
{
    const int pix = blockIdx.x * 256 + threadIdx.x;
    const int b   = blockIdx.z;

    const float* src = img + (size_t)b * CC * HWSZ + pix;

    float v[CC];
    #pragma unroll
    for (int c = 0; c < CC; ++c)
        v[c] = __ldcs(src + (size_t)c * HWSZ);

    __half2 h[8];
    #pragma unroll
    for (int i = 0; i < 8; ++i)
        h[i] = __floats2half2_rn(v[2 * i], v[2 * i + 1]);

    uint4* dst = (uint4*)(g_buf + 16) + ((size_t)b * HWSZ + pix) * 2;
    dst[0] = *(uint4*)&h[0];
    dst[1] = *(uint4*)&h[4];
}

// ---------------------------------------------------------------------------
// Kernel 2: gather, all batches. Lane = (j, g): j=0..3 splits the 64B
// (rec(x0)|rec(x1)) span per corner row, g = 4-pixel group; thread owns
// 4 pixels x 4 channels. side = j>>1 (x0/x1 record), chalf = j&1.
// Loads:  ~2.5 line-visits/pixel. Stores: plane-major STG.128, 0.5 wf/px.
// (round-10 body verbatim; launch bounds raise occupancy 53% -> ~75%)
// ---------------------------------------------------------------------------
__global__ __launch_bounds__(256, 6) void gather_kernel(
    const float* __restrict__ flo,
    float* __restrict__ out)
{
    const int tid   = threadIdx.x;
    const int lane  = tid & 31;
    const int warp  = tid >> 5;
    const int j     = lane & 3;
    const int g     = lane >> 2;
    const int side  = j >> 1;
    const int chalf = j & 1;

    const int pix0 = (blockIdx.x * 8 + warp) * 32 + g * 4;   // 16B-aligned
    const int b    = blockIdx.z;
    const int x0p  = pix0 & (WW - 1);
    const int yrow = pix0 >> 9;

    const float* flob = flo + (size_t)b * 2 * HWSZ;
    const float4 u = __ldg((const float4*)(flob + pix0));
    const float4 v = __ldg((const float4*)(flob + HWSZ + pix0));
    const float uu[4] = {u.x, u.y, u.z, u.w};
    const float vv[4] = {v.x, v.y, v.z, v.w};

    const uint4* recs4 = (const uint4*)(g_buf + 16);
    const int rb = b * HWSZ;

    float acc[4][4];   // [channel-in-quad][pixel]

    #pragma unroll
    for (int p = 0; p < 4; ++p) {
        const float gx = (float)(x0p + p) + uu[p];
        const float gy = (float)yrow + vv[p];

        const float x0f = floorf(gx);
        const float y0f = floorf(gy);
        const float x1f = x0f + 1.0f;
        const float y1f = y0f + 1.0f;

        const float wx1 = gx - x0f, wx0 = 1.0f - wx1;
        const float wy1 = gy - y0f, wy0 = 1.0f - wy1;

        const float vx0 = (x0f >= 0.0f && x0f <= 511.0f) ? 1.0f : 0.0f;
        const float vx1 = (x1f >= 0.0f && x1f <= 511.0f) ? 1.0f : 0.0f;
        const float vy0 = (y0f >= 0.0f && y0f <= 511.0f) ? 1.0f : 0.0f;
        const float vy1 = (y1f >= 0.0f && y1f <= 511.0f) ? 1.0f : 0.0f;

        const float a0 = wx0 * vx0, a1 = wx1 * vx1;
        float       b0 = wy0 * vy0, b1 = wy1 * vy1;

        // mask in the reference's exact op order (f32 throughout)
        const float w00 = a0 * b0, w10 = a1 * b0, w01 = a0 * b1, w11 = a1 * b1;
        const float mask = ((w00 + w10) + w01) + w11;

        // Branch-free zeroing: keeps warp converged for the shuffles below.
        const float zm = (mask < 0.9999f) ? 0.0f : 1.0f;
        b0 *= zm;  b1 *= zm;

        // Span base: record floor(gx), clamped to [-1, 511]; pads absorb edges.
        const int bx  = (int)fminf(fmaxf(x0f, -1.0f), 511.0f);
        const int y0i = (int)fminf(fmaxf(y0f,        0.0f), 511.0f);
        const int y1i = (int)fminf(fmaxf(y0f + 1.0f, 0.0f), 511.0f);

        const long ti = (long)(rb + y0i * WW + bx) * 2 + j;
        const long bi = (long)(rb + y1i * WW + bx) * 2 + j;

        const uint4 t4  = __ldg(recs4 + ti);
        const uint4 bt4 = __ldg(recs4 + bi);

        const __half2* th = (const __half2*)&t4;
        const __half2* bh = (const __half2*)&bt4;

        const float as = side ? a1 : a0;

        float r[8];
        #pragma unroll
        for (int q = 0; q < 4; ++q) {
            const float2 tf = __half22float2(th[q]);
            const float2 bf = __half22float2(bh[q]);
            float fx = as * (b0 * tf.x + b1 * bf.x);
            float fy = as * (b0 * tf.y + b1 * bf.y);
            fx += __shfl_xor_sync(0xffffffffu, fx, 2);
            fy += __shfl_xor_sync(0xffffffffu, fy, 2);
            r[2 * q]     = fx;
            r[2 * q + 1] = fy;
        }

        // Lane keeps channels chalf*8 + side*4 .. +3  ->  r[side*4 + k]
        acc[0][p] = r[side * 4 + 0];
        acc[1][p] = r[side * 4 + 1];
        acc[2][p] = r[side * 4 + 2];
        acc[3][p] = r[side * 4 + 3];
    }

    const int cbase = chalf * 8 + side * 4;
    float* ob = out + (size_t)b * CC * HWSZ + pix0;
    #pragma unroll
    for (int k = 0; k < 4; ++k) {
        const float4 o = make_float4(acc[k][0], acc[k][1], acc[k][2], acc[k][3]);
        __stcs((float4*)(ob + (size_t)(cbase + k) * HWSZ), o);
    }
}

extern "C" void kernel_launch(void* const* d_in, const int* in_sizes, int n_in,
                              void* d_out, int out_size)
{
    const float* img = (const float*)d_in[0];
    const float* flo = (const float*)d_in[1];
    float* out = (float*)d_out;

    dim3 gridT(HWSZ / 256, 1, BB);
    transpose_kernel<<<gridT, 256>>>(img);

    dim3 gridG(HWSZ / 256, 1, BB);   // 8192 CTAs
    gather_kernel<<<gridG, 256>>>(flo, out);
}

// round 15
// speedup vs baseline: 1.0714x; 1.0714x over previous
#include <cuda_runtime.h>
#include <cuda_fp16.h>

// image [8,16,512,512] f32, flow [8,2,512,512] f32, out [8,16,512,512] f32
#define BB 8
#define CC 16
#define HH 512
#define WW 512
#define HWSZ (HH * WW)

// fp16 NHWC scratch with 32B front/back pads (zero-initialized, never written).
// Record = 16 ch * 2B = 32B per pixel.
__device__ __align__(16) __half g_buf[16 + (size_t)BB * HWSZ * CC + 16];

// ---------------------------------------------------------------------------
// Kernel 1: NCHW f32 -> NHWC fp16, all batches. Thread-per-pixel.
// (round-10 body verbatim)
// ---------------------------------------------------------------------------
__global__ __launch_bounds__(256) void transpose_kernel(
    const float* __restrict__ img)
{
    const int pix = blockIdx.x * 256 + threadIdx.x;
    const int b   = blockIdx.z;

    const float* src = img + (size_t)b * CC * HWSZ + pix;

    float v[CC];
    #pragma unroll
    for (int c = 0; c < CC; ++c)
        v[c] = __ldcs(src + (size_t)c * HWSZ);

    __half2 h[8];
    #pragma unroll
    for (int i = 0; i < 8; ++i)
        h[i] = __floats2half2_rn(v[2 * i], v[2 * i + 1]);

    uint4* dst = (uint4*)(g_buf + 16) + ((size_t)b * HWSZ + pix) * 2;
    dst[0] = *(uint4*)&h[0];
    dst[1] = *(uint4*)&h[4];
}

// ---------------------------------------------------------------------------
// Kernel 2: gather (round-10 math) restructured into two phases:
// Phase A: weights + ALL 8 span loads issued (MLP = 8 per thread).
// Phase B: shfl x-combine + FMA consume.
// Lane = (j, g): j splits the 64B (rec(x0)|rec(x1)) span, g = 4-pixel group.
// ---------------------------------------------------------------------------
__global__ __launch_bounds__(256) void gather_kernel(
    const float* __restrict__ flo,
    float* __restrict__ out)
{
    const int tid   = threadIdx.x;
    const int lane  = tid & 31;
    const int warp  = tid >> 5;
    const int j     = lane & 3;
    const int g     = lane >> 2;
    const int side  = j >> 1;
    const int chalf = j & 1;

    const int pix0 = (blockIdx.x * 8 + warp) * 32 + g * 4;   // 16B-aligned
    const int b    = blockIdx.z;
    const int x0p  = pix0 & (WW - 1);
    const int yrow = pix0 >> 9;

    const float* flob = flo + (size_t)b * 2 * HWSZ;
    const float4 u = __ldg((const float4*)(flob + pix0));
    const float4 v = __ldg((const float4*)(flob + HWSZ + pix0));
    const float uu[4] = {u.x, u.y, u.z, u.w};
    const float vv[4] = {v.x, v.y, v.z, v.w};

    const uint4* recs4 = (const uint4*)(g_buf + 16);
    const int rb = b * HWSZ;

    // ---------------- Phase A: weights + all loads in flight -----------------
    float AS[4], B0[4], B1[4];
    uint4 T4[4], BT4[4];

    #pragma unroll
    for (int p = 0; p < 4; ++p) {
        const float gx = (float)(x0p + p) + uu[p];
        const float gy = (float)yrow + vv[p];

        const float x0f = floorf(gx);
        const float y0f = floorf(gy);
        const float x1f = x0f + 1.0f;
        const float y1f = y0f + 1.0f;

        const float wx1 = gx - x0f, wx0 = 1.0f - wx1;
        const float wy1 = gy - y0f, wy0 = 1.0f - wy1;

        const float vx0 = (x0f >= 0.0f && x0f <= 511.0f) ? 1.0f : 0.0f;
        const float vx1 = (x1f >= 0.0f && x1f <= 511.0f) ? 1.0f : 0.0f;
        const float vy0 = (y0f >= 0.0f && y0f <= 511.0f) ? 1.0f : 0.0f;
        const float vy1 = (y1f >= 0.0f && y1f <= 511.0f) ? 1.0f : 0.0f;

        const float a0 = wx0 * vx0, a1 = wx1 * vx1;
        float       b0 = wy0 * vy0, b1 = wy1 * vy1;

        // mask in the reference's exact op order (f32 throughout)
        const float w00 = a0 * b0, w10 = a1 * b0, w01 = a0 * b1, w11 = a1 * b1;
        const float mask = ((w00 + w10) + w01) + w11;

        const float zm = (mask < 0.9999f) ? 0.0f : 1.0f;
        b0 *= zm;  b1 *= zm;

        B0[p] = b0;  B1[p] = b1;
        AS[p] = side ? a1 : a0;

        // Span base: record floor(gx), clamped to [-1, 511]; pads absorb edges.
        const int bx  = (int)fminf(fmaxf(x0f, -1.0f), 511.0f);
        const int y0i = (int)fminf(fmaxf(y0f,        0.0f), 511.0f);
        const int y1i = (int)fminf(fmaxf(y0f + 1.0f, 0.0f), 511.0f);

        const long ti = (long)(rb + y0i * WW + bx) * 2 + j;
        const long bi = (long)(rb + y1i * WW + bx) * 2 + j;

        T4[p]  = __ldg(recs4 + ti);
        BT4[p] = __ldg(recs4 + bi);
    }

    // ---------------- Phase B: consume ---------------------------------------
    float acc[4][4];   // [channel-in-quad][pixel]

    #pragma unroll
    for (int p = 0; p < 4; ++p) {
        const __half2* th = (const __half2*)&T4[p];
        const __half2* bh = (const __half2*)&BT4[p];
        const float b0 = B0[p], b1 = B1[p], as = AS[p];

        float r[8];
        #pragma unroll
        for (int q = 0; q < 4; ++q) {
            const float2 tf = __half22float2(th[q]);
            const float2 bf = __half22float2(bh[q]);
            float fx = as * (b0 * tf.x + b1 * bf.x);
            float fy = as * (b0 * tf.y + b1 * bf.y);
            fx += __shfl_xor_sync(0xffffffffu, fx, 2);
            fy += __shfl_xor_sync(0xffffffffu, fy, 2);
            r[2 * q]     = fx;
            r[2 * q + 1] = fy;
        }

        acc[0][p] = r[side * 4 + 0];
        acc[1][p] = r[side * 4 + 1];
        acc[2][p] = r[side * 4 + 2];
        acc[3][p] = r[side * 4 + 3];
    }

    const int cbase = chalf * 8 + side * 4;
    float* ob = out + (size_t)b * CC * HWSZ + pix0;
    #pragma unroll
    for (int k = 0; k < 4; ++k) {
        const float4 o = make_float4(acc[k][0], acc[k][1], acc[k][2], acc[k][3]);
        __stcs((float4*)(ob + (size_t)(cbase + k) * HWSZ), o);
    }
}

extern "C" void kernel_launch(void* const* d_in, const int* in_sizes, int n_in,
                              void* d_out, int out_size)
{
    const float* img = (const float*)d_in[0];
    const float* flo = (const float*)d_in[1];
    float* out = (float*)d_out;

    dim3 gridT(HWSZ / 256, 1, BB);
    transpose_kernel<<<gridT, 256>>>(img);

    dim3 gridG(HWSZ / 256, 1, BB);   // 8192 CTAs
    gather_kernel<<<gridG, 256>>>(flo, out);
}

// round 16
// speedup vs baseline: 1.1243x; 1.0493x over previous
#include <cuda_runtime.h>
#include <cuda_fp16.h>

// image [8,16,512,512] f32, flow [8,2,512,512] f32, out [8,16,512,512] f32
#define BB 8
#define CC 16
#define HH 512
#define WW 512
#define HWSZ (HH * WW)

// fp16 NHWC scratch with 32B front/back pads (zero-initialized, never written).
// Record = 16 ch * 2B = 32B per pixel.
__device__ __align__(16) __half g_buf[16 + (size_t)BB * HWSZ * CC + 16];

// ---------------------------------------------------------------------------
// Kernel 1: NCHW f32 -> NHWC fp16, all batches. Thread-per-pixel.
// (round-10 body verbatim — best measured transpose)
// ---------------------------------------------------------------------------
__global__ __launch_bounds__(256) void transpose_kernel(
    const float* __restrict__ img)
{
    const int pix = blockIdx.x * 256 + threadIdx.x;
    const int b   = blockIdx.z;

    const float* src = img + (size_t)b * CC * HWSZ + pix;

    float v[CC];
    #pragma unroll
    for (int c = 0; c < CC; ++c)
        v[c] = __ldcs(src + (size_t)c * HWSZ);

    __half2 h[8];
    #pragma unroll
    for (int i = 0; i < 8; ++i)
        h[i] = __floats2half2_rn(v[2 * i], v[2 * i + 1]);

    uint4* dst = (uint4*)(g_buf + 16) + ((size_t)b * HWSZ + pix) * 2;
    dst[0] = *(uint4*)&h[0];
    dst[1] = *(uint4*)&h[4];
}

// ---------------------------------------------------------------------------
// Kernel 2: gather (round-10 structure). Lane = (j, g): j=0..3 splits the
// 64B (rec(x0)|rec(x1)) span, g = 4-pixel group. side=j>>1, chalf=j&1.
// HALF-EXCHANGE: instead of 8 symmetric shfl_xor per p (half the results
// discarded), each lane sends its contribution to the PARTNER's kept
// channel-quad and receives the partner's contribution to its own quad:
// 4 shfl per p. out[k] = c[side*4+k] + shfl_xor(c[(1-side)*4+k], 2).
// ---------------------------------------------------------------------------
__global__ __launch_bounds__(256) void gather_kernel(
    const float* __restrict__ flo,
    float* __restrict__ out)
{
    const int tid   = threadIdx.x;
    const int lane  = tid & 31;
    const int warp  = tid >> 5;
    const int j     = lane & 3;
    const int g     = lane >> 2;
    const int side  = j >> 1;
    const int chalf = j & 1;

    const int pix0 = (blockIdx.x * 8 + warp) * 32 + g * 4;   // 16B-aligned
    const int b    = blockIdx.z;
    const int x0p  = pix0 & (WW - 1);
    const int yrow = pix0 >> 9;

    const float* flob = flo + (size_t)b * 2 * HWSZ;
    const float4 u = __ldg((const float4*)(flob + pix0));
    const float4 v = __ldg((const float4*)(flob + HWSZ + pix0));
    const float uu[4] = {u.x, u.y, u.z, u.w};
    const float vv[4] = {v.x, v.y, v.z, v.w};

    const uint4* recs4 = (const uint4*)(g_buf + 16);
    const int rb = b * HWSZ;

    float acc[4][4];   // [channel-in-quad][pixel]

    #pragma unroll
    for (int p = 0; p < 4; ++p) {
        const float gx = (float)(x0p + p) + uu[p];
        const float gy = (float)yrow + vv[p];

        const float x0f = floorf(gx);
        const float y0f = floorf(gy);
        const float x1f = x0f + 1.0f;
        const float y1f = y0f + 1.0f;

        const float wx1 = gx - x0f, wx0 = 1.0f - wx1;
        const float wy1 = gy - y0f, wy0 = 1.0f - wy1;

        const float vx0 = (x0f >= 0.0f && x0f <= 511.0f) ? 1.0f : 0.0f;
        const float vx1 = (x1f >= 0.0f && x1f <= 511.0f) ? 1.0f : 0.0f;
        const float vy0 = (y0f >= 0.0f && y0f <= 511.0f) ? 1.0f : 0.0f;
        const float vy1 = (y1f >= 0.0f && y1f <= 511.0f) ? 1.0f : 0.0f;

        const float a0 = wx0 * vx0, a1 = wx1 * vx1;
        float       b0 = wy0 * vy0, b1 = wy1 * vy1;

        // mask in the reference's exact op order (f32 throughout)
        const float w00 = a0 * b0, w10 = a1 * b0, w01 = a0 * b1, w11 = a1 * b1;
        const float mask = ((w00 + w10) + w01) + w11;

        // Branch-free zeroing: keeps warp converged for the shuffles below.
        const float zm = (mask < 0.9999f) ? 0.0f : 1.0f;
        b0 *= zm;  b1 *= zm;

        // Span base: record floor(gx), clamped to [-1, 511]; pads absorb edges.
        const int bx  = (int)fminf(fmaxf(x0f, -1.0f), 511.0f);
        const int y0i = (int)fminf(fmaxf(y0f,        0.0f), 511.0f);
        const int y1i = (int)fminf(fmaxf(y0f + 1.0f, 0.0f), 511.0f);

        const long ti = (long)(rb + y0i * WW + bx) * 2 + j;
        const long bi = (long)(rb + y1i * WW + bx) * 2 + j;

        const uint4 t4  = __ldg(recs4 + ti);
        const uint4 bt4 = __ldg(recs4 + bi);

        const __half2* th = (const __half2*)&t4;
        const __half2* bh = (const __half2*)&bt4;

        const float as = side ? a1 : a0;

        // My contribution to my 8 channels (chalf*8 .. +7) from rec(x_side).
        float c[8];
        #pragma unroll
        for (int q = 0; q < 4; ++q) {
            const float2 tf = __half22float2(th[q]);
            const float2 bf = __half22float2(bh[q]);
            c[2 * q]     = as * (b0 * tf.x + b1 * bf.x);
            c[2 * q + 1] = as * (b0 * tf.y + b1 * bf.y);
        }

        // Half-exchange: send contribution to partner's kept quad, receive
        // partner's contribution to mine. Partner = lane ^ 2 (other side).
        #pragma unroll
        for (int k = 0; k < 4; ++k) {
            const float keep = side ? c[4 + k] : c[k];
            const float send = side ? c[k]     : c[4 + k];
            acc[k][p] = keep + __shfl_xor_sync(0xffffffffu, send, 2);
        }
    }

    const int cbase = chalf * 8 + side * 4;
    float* ob = out + (size_t)b * CC * HWSZ + pix0;
    #pragma unroll
    for (int k = 0; k < 4; ++k) {
        const float4 o = make_float4(acc[k][0], acc[k][1], acc[k][2], acc[k][3]);
        __stcs((float4*)(ob + (size_t)(cbase + k) * HWSZ), o);
    }
}

extern "C" void kernel_launch(void* const* d_in, const int* in_sizes, int n_in,
                              void* d_out, int out_size)
{
    const float* img = (const float*)d_in[0];
    const float* flo = (const float*)d_in[1];
    float* out = (float*)d_out;

    dim3 gridT(HWSZ / 256, 1, BB);
    transpose_kernel<<<gridT, 256>>>(img);

    dim3 gridG(HWSZ / 256, 1, BB);   // 8192 CTAs
    gather_kernel<<<gridG, 256>>>(flo, out);
}